// round 1
// baseline (speedup 1.0000x reference)
#include <cuda_runtime.h>
#include <stdint.h>

#define CIN  320
#define COUT 320
#define HWSZ 4096         // 64*64
#define NPIX 65536        // 16 * 4096
#define KTAPS 9

// Scratch (allocation-free rule: __device__ globals)
__device__ int8_t g_xq[(size_t)NPIX * CIN];       // [pix][ci]  (NHWC)
__device__ int8_t g_wq[(size_t)KTAPS * COUT * CIN]; // [kpos][co][ci]
__device__ float  g_bint8[COUT];

__device__ __forceinline__ float clamp127(float v) {
    return fminf(127.0f, fmaxf(-127.0f, v));
}

// ---------------------------------------------------------------------------
// Kernel 1: quantize x  (NCHW fp32 -> NHWC int8)
// grid (NPIX/256, 80), block 256. Reads coalesced, writes char4 scattered.
// ---------------------------------------------------------------------------
__global__ void quant_x_kernel(const float* __restrict__ x,
                               const float* __restrict__ step_x) {
    float s = *step_x;
    int pix = blockIdx.x * 256 + threadIdx.x;   // 0..65535
    int cg  = blockIdx.y;                        // 0..79 (groups of 4 channels)
    int n   = pix >> 12;
    int hw  = pix & 4095;
    const float* xp = x + ((size_t)(n * CIN + cg * 4)) * HWSZ + hw;

    float v0 = clamp127(rintf(__fdiv_rn(xp[0 * HWSZ], s)));
    float v1 = clamp127(rintf(__fdiv_rn(xp[1 * HWSZ], s)));
    float v2 = clamp127(rintf(__fdiv_rn(xp[2 * HWSZ], s)));
    float v3 = clamp127(rintf(__fdiv_rn(xp[3 * HWSZ], s)));

    char4 q;
    q.x = (signed char)v0; q.y = (signed char)v1;
    q.z = (signed char)v2; q.w = (signed char)v3;
    *(char4*)(g_xq + (size_t)pix * CIN + cg * 4) = q;
}

// ---------------------------------------------------------------------------
// Kernel 2: quantize w  (OIHW fp32 -> [kpos][co][ci] int8)
// ---------------------------------------------------------------------------
__global__ void quant_w_kernel(const float* __restrict__ w,
                               const float* __restrict__ step_w) {
    float s = *step_w;
    int idx = blockIdx.x * 256 + threadIdx.x;
    if (idx >= KTAPS * COUT * CIN) return;
    int kpos = idx / (COUT * CIN);
    int r    = idx % (COUT * CIN);
    int co   = r / CIN;
    int ci   = r % CIN;
    float v = clamp127(rintf(__fdiv_rn(w[(size_t)(co * CIN + ci) * KTAPS + kpos], s)));
    g_wq[idx] = (int8_t)v;
}

// ---------------------------------------------------------------------------
// Kernel 3: quantized bias (per output channel)
// b_int8 = clip(rint( clip(rint(b/sb),±127)*sb * shift * (1/sx) * (1/sw) ), ±127)
// ---------------------------------------------------------------------------
__global__ void bias_kernel(const float* __restrict__ bias,
                            const float* __restrict__ step_b,
                            const float* __restrict__ step_x,
                            const float* __restrict__ step_w,
                            const float* __restrict__ shift) {
    int co = blockIdx.x * blockDim.x + threadIdx.x;
    if (co >= COUT) return;
    float sb = *step_b;
    float xs = __fdiv_rn(1.0f, *step_x);
    float ws = __fdiv_rn(1.0f, *step_w);
    float sh = *shift;
    float bi   = clamp127(rintf(__fdiv_rn(bias[co], sb)));
    float bdeq = __fmul_rn(bi, sb);
    float t = __fmul_rn(__fmul_rn(__fmul_rn(bdeq, sh), xs), ws);
    g_bint8[co] = clamp127(rintf(t));
}

// ---------------------------------------------------------------------------
// Kernel 4: implicit-GEMM int8 conv with mma.sync m16n8k32
//   M = Cout (tile 64), N = pixels (tile 128), K = 9 taps x 320 ci
//   block 256 = 8 warps, warp grid 2(m) x 4(n), warp tile 32co x 32pix
// ---------------------------------------------------------------------------
__device__ __forceinline__ void mma_s8(int* c, const uint32_t* a, const uint32_t* b) {
    asm volatile(
        "mma.sync.aligned.m16n8k32.row.col.s32.s8.s8.s32 "
        "{%0,%1,%2,%3}, {%4,%5,%6,%7}, {%8,%9}, {%0,%1,%2,%3};"
        : "+r"(c[0]), "+r"(c[1]), "+r"(c[2]), "+r"(c[3])
        : "r"(a[0]), "r"(a[1]), "r"(a[2]), "r"(a[3]),
          "r"(b[0]), "r"(b[1]));
}

__global__ __launch_bounds__(256, 2)
void conv_mma_kernel(float* __restrict__ out,
                     const float* __restrict__ shift_ptr) {
    __shared__ __align__(16) int8_t sA[64 * 32];    // [co][ci32]  (weights)
    __shared__ __align__(16) int8_t sB[128 * 32];   // [pix][ci32] (activations)
    const uint32_t* sA32 = (const uint32_t*)sA;
    const uint32_t* sB32 = (const uint32_t*)sB;

    const int tid  = threadIdx.x;
    const int wid  = tid >> 5;
    const int lane = tid & 31;
    const int warp_m = wid >> 2;     // 0..1
    const int warp_n = wid & 3;      // 0..3
    const int co_base  = blockIdx.y * 64;
    const int pix_base = blockIdx.x * 128;

    int acc[2][4][4];
#pragma unroll
    for (int i = 0; i < 2; i++)
#pragma unroll
        for (int j = 0; j < 4; j++)
#pragma unroll
            for (int k = 0; k < 4; k++) acc[i][j][k] = 0;

    // B-load coords: thread -> (pixel, half)
    const int pB   = tid >> 1;       // 0..127
    const int half = tid & 1;
    const int gp = pix_base + pB;
    const int n  = gp >> 12;
    const int hw = gp & 4095;
    const int h  = hw >> 6;
    const int w  = hw & 63;

    // A-load coords: first 128 threads -> (co, half)
    const int coA = tid >> 1;        // valid when tid < 128 (coA 0..63)

    const int qq = lane & 3;   // thread-in-group
    const int rr = lane >> 2;  // group id

    for (int kpos = 0; kpos < KTAPS; ++kpos) {
        const int dh = kpos / 3 - 1;
        const int dw = kpos % 3 - 1;
        const int hs = h + dh;
        const int ws = w + dw;
        const bool inb = (hs >= 0) && (hs < 64) && (ws >= 0) && (ws < 64);
        const int8_t* srcB = g_xq + (size_t)((n << 12) + (hs << 6) + ws) * CIN;
        const int8_t* srcA = g_wq + ((size_t)kpos * COUT + co_base + coA) * CIN;

        for (int ck = 0; ck < 10; ++ck) {
            // ---- stage tiles into smem ----
            if (tid < 128) {
                int4 av = *(const int4*)(srcA + ck * 32 + half * 16);
                *(int4*)(sA + coA * 32 + half * 16) = av;
            }
            int4 bv = make_int4(0, 0, 0, 0);
            if (inb) bv = *(const int4*)(srcB + ck * 32 + half * 16);
            *(int4*)(sB + pB * 32 + half * 16) = bv;
            __syncthreads();

            // ---- fragments ----
            uint32_t a[2][4], b[4][2];
#pragma unroll
            for (int mt = 0; mt < 2; mt++) {
                int row = warp_m * 32 + mt * 16 + rr;
                a[mt][0] = sA32[row * 8 + qq];
                a[mt][1] = sA32[(row + 8) * 8 + qq];
                a[mt][2] = sA32[row * 8 + 4 + qq];
                a[mt][3] = sA32[(row + 8) * 8 + 4 + qq];
            }
#pragma unroll
            for (int nt = 0; nt < 4; nt++) {
                int col = warp_n * 32 + nt * 8 + rr;
                b[nt][0] = sB32[col * 8 + qq];
                b[nt][1] = sB32[col * 8 + 4 + qq];
            }
#pragma unroll
            for (int mt = 0; mt < 2; mt++)
#pragma unroll
                for (int nt = 0; nt < 4; nt++)
                    mma_s8(acc[mt][nt], a[mt], b[nt]);
            __syncthreads();
        }
    }

    // ---- epilogue: shift, round, clip, +bias_int8, clip; write NCHW fp32 ----
    const float shift = *shift_ptr;
#pragma unroll
    for (int mt = 0; mt < 2; mt++) {
#pragma unroll
        for (int hh = 0; hh < 2; hh++) {
            int co = co_base + warp_m * 32 + mt * 16 + rr + hh * 8;
            float bb = g_bint8[co];
#pragma unroll
            for (int nt = 0; nt < 4; nt++) {
                int pix  = pix_base + warp_n * 32 + nt * 8 + qq * 2;
                int nimg = pix >> 12;
                int ohw  = pix & 4095;
                float* op = out + (((size_t)(nimg * COUT + co)) << 12) + ohw;
                int a0 = acc[mt][nt][hh * 2 + 0];
                int a1 = acc[mt][nt][hh * 2 + 1];
                float v0 = clamp127(rintf(__int2float_rn(a0) * shift));
                float v1 = clamp127(rintf(__int2float_rn(a1) * shift));
                v0 = clamp127(v0 + bb);
                v1 = clamp127(v1 + bb);
                *(float2*)op = make_float2(v0, v1);
            }
        }
    }
}

// ---------------------------------------------------------------------------
extern "C" void kernel_launch(void* const* d_in, const int* in_sizes, int n_in,
                              void* d_out, int out_size) {
    const float* x      = (const float*)d_in[0];
    const float* wt     = (const float*)d_in[1];
    const float* bias   = (const float*)d_in[2];
    const float* step_x = (const float*)d_in[3];
    const float* step_w = (const float*)d_in[4];
    const float* step_b = (const float*)d_in[5];
    const float* shift  = (const float*)d_in[6];
    float* out = (float*)d_out;

    dim3 gq(NPIX / 256, CIN / 4);
    quant_x_kernel<<<gq, 256>>>(x, step_x);

    int wtotal = KTAPS * COUT * CIN;
    quant_w_kernel<<<(wtotal + 255) / 256, 256>>>(wt, step_w);

    bias_kernel<<<2, 160>>>(bias, step_b, step_x, step_w, shift);

    dim3 gc(NPIX / 128, COUT / 64);
    conv_mma_kernel<<<gc, 256>>>(out, shift);
}

// round 3
// speedup vs baseline: 1.1300x; 1.1300x over previous
#include <cuda_runtime.h>
#include <stdint.h>

#define CIN   320
#define COUT  320
#define KTAPS 9
#define NPIX  65536
#define HWSZ  4096

// scratch (__device__ globals: allocation-free rule)
__device__ __align__(128) int8_t g_xq[(size_t)NPIX * CIN];          // [pix][ci]
__device__ __align__(128) int8_t g_wq[(size_t)KTAPS * COUT * CIN];  // [kpos][co][ci]
__device__ float g_bint8[COUT];

__device__ __forceinline__ float clamp127(float v) {
    return fminf(127.0f, fmaxf(-127.0f, v));
}

// ---------------------------------------------------------------------------
// Kernel 1: quantize x (NCHW fp32 -> NHWC int8) via smem transpose.
// grid (1024, 5), block 256. Tile: 64 channels x 64 pixels.
// ---------------------------------------------------------------------------
#define QP 80
__global__ __launch_bounds__(256) void quant_x_kernel(const float* __restrict__ x,
                                                      const float* __restrict__ step_x) {
    __shared__ int8_t s[64 * QP];
    const float st = *step_x;
    const int tid = threadIdx.x;
    const int ptile = blockIdx.x;          // 64-pixel tile (1024 total)
    const int ctile = blockIdx.y;          // 64-channel tile (5 total)
    const int n = ptile >> 6;
    const int hw0 = (ptile & 63) << 6;
    const float* xb = x + (((size_t)(n * CIN + ctile * 64)) << 12) + hw0;

#pragma unroll
    for (int k = 0; k < 4; k++) {
        int idx = tid + 256 * k;           // float4 index 0..1023
        int ci = idx >> 4;                 // 0..63
        int p4 = (idx & 15) << 2;          // pixel base
        float4 f = *(const float4*)(xb + (((size_t)ci) << 12) + p4);
        s[(p4 + 0) * QP + ci] = (int8_t)clamp127(rintf(__fdiv_rn(f.x, st)));
        s[(p4 + 1) * QP + ci] = (int8_t)clamp127(rintf(__fdiv_rn(f.y, st)));
        s[(p4 + 2) * QP + ci] = (int8_t)clamp127(rintf(__fdiv_rn(f.z, st)));
        s[(p4 + 3) * QP + ci] = (int8_t)clamp127(rintf(__fdiv_rn(f.w, st)));
    }
    __syncthreads();
    {
        int p = tid >> 2;
        int ch = (tid & 3) * 16;
        int4 v = *(const int4*)(s + p * QP + ch);
        *(int4*)(g_xq + (size_t)((n << 12) + hw0 + p) * CIN + ctile * 64 + ch) = v;
    }
}

// ---------------------------------------------------------------------------
// Kernel 2: quantize w  (OIHW fp32 -> [kpos][co][ci] int8)
// ---------------------------------------------------------------------------
__global__ void quant_w_kernel(const float* __restrict__ w,
                               const float* __restrict__ step_w) {
    float s = *step_w;
    int idx = blockIdx.x * 256 + threadIdx.x;
    if (idx >= KTAPS * COUT * CIN) return;
    int kpos = idx / (COUT * CIN);
    int r = idx % (COUT * CIN);
    int co = r / CIN;
    int ci = r % CIN;
    float v = clamp127(rintf(__fdiv_rn(w[(size_t)(co * CIN + ci) * KTAPS + kpos], s)));
    g_wq[idx] = (int8_t)v;
}

// ---------------------------------------------------------------------------
// Kernel 3: quantized bias
// ---------------------------------------------------------------------------
__global__ void bias_kernel(const float* __restrict__ bias,
                            const float* __restrict__ step_b,
                            const float* __restrict__ step_x,
                            const float* __restrict__ step_w,
                            const float* __restrict__ shift) {
    int co = blockIdx.x * blockDim.x + threadIdx.x;
    if (co >= COUT) return;
    float sb = *step_b;
    float xs = __fdiv_rn(1.0f, *step_x);
    float ws = __fdiv_rn(1.0f, *step_w);
    float sh = *shift;
    float bi = clamp127(rintf(__fdiv_rn(bias[co], sb)));
    float bdeq = __fmul_rn(bi, sb);
    float t = __fmul_rn(__fmul_rn(__fmul_rn(bdeq, sh), xs), ws);
    g_bint8[co] = clamp127(rintf(t));
}

// ---------------------------------------------------------------------------
// Kernel 4: HYBRID conv — IMMA warps (tensor pipe) + dp4a warps (ALU pipe)
//   CTA tile: 64 cout x 128 pixels.
//   warps 0..7 (256 thr): mma.sync m16n8k32 over taps [0, TAPS_I)
//   warps 8..11 (128 thr): dp4a 8co x 8pix register tiles over taps [TAPS_I, 9)
//   dp4a partials -> smem pint, merged in IMMA epilogue.
// ---------------------------------------------------------------------------
#define TAPS_I 6
#define NSI (TAPS_I * 10)
#define NSD ((KTAPS - TAPS_I) * 10)

__device__ __forceinline__ void mma_s8(int* c, const uint32_t* a, const uint32_t* b) {
    asm volatile(
        "mma.sync.aligned.m16n8k32.row.col.s32.s8.s8.s32 "
        "{%0,%1,%2,%3}, {%4,%5,%6,%7}, {%8,%9}, {%0,%1,%2,%3};"
        : "+r"(c[0]), "+r"(c[1]), "+r"(c[2]), "+r"(c[3])
        : "r"(a[0]), "r"(a[1]), "r"(a[2]), "r"(a[3]),
          "r"(b[0]), "r"(b[1]));
}

__global__ __launch_bounds__(384, 1)
void conv_hybrid_kernel(float* __restrict__ out, const float* __restrict__ shift_ptr) {
    __shared__ __align__(16) int8_t sAi[64 * 32];    // IMMA weights stage
    __shared__ __align__(16) int8_t sBi[128 * 32];   // IMMA activations stage
    __shared__ __align__(16) int8_t sAd[64 * 32];    // dp4a weights stage
    __shared__ __align__(16) int8_t sBd[128 * 32];   // dp4a activations stage
    __shared__ int pint[64 * 128];                   // dp4a partial sums [co][pix]

    const int tid = threadIdx.x;
    const int pix_base = blockIdx.x * 128;
    const int co_base = blockIdx.y * 64;
    const int n = pix_base >> 12;
    const int H0 = (pix_base & 4095) >> 6;   // CTA covers rows H0, H0+1

    int acc[2][4][4];   // IMMA accumulators (only used by tid<256)

    if (tid < 256) {
        // ======================= IMMA group =======================
        const int wid = tid >> 5, lane = tid & 31;
        const int warp_m = wid >> 2, warp_n = wid & 3;
        const int qq = lane & 3, rr = lane >> 2;
        const uint32_t* sA32 = (const uint32_t*)sAi;
        const uint32_t* sB32 = (const uint32_t*)sBi;

#pragma unroll
        for (int i = 0; i < 2; i++)
#pragma unroll
            for (int j = 0; j < 4; j++)
#pragma unroll
                for (int k = 0; k < 4; k++) acc[i][j][k] = 0;

        const int rowT = tid >> 1;     // A co-row (tid<128) and B pixel row
        const int half = tid & 1;
        const int hB = H0 + (rowT >> 6);
        const int wB = rowT & 63;

        int4 av, bv;
        // prefetch stage 0 (kpos=0 -> dh=-1, dw=-1, ck=0)
        {
            if (tid < 128)
                av = *(const int4*)(g_wq + ((size_t)(co_base + rowT)) * CIN + half * 16);
            int hs = hB - 1, ws = wB - 1;
            bv = make_int4(0, 0, 0, 0);
            if (hs >= 0 && hs < 64 && ws >= 0 && ws < 64)
                bv = *(const int4*)(g_xq + (size_t)((n << 12) + (hs << 6) + ws) * CIN + half * 16);
        }

        for (int i = 0; i < NSI; i++) {
            asm volatile("bar.sync 1, 256;" ::: "memory");
            if (tid < 128) *(int4*)(sAi + rowT * 32 + half * 16) = av;
            *(int4*)(sBi + rowT * 32 + half * 16) = bv;
            asm volatile("bar.sync 1, 256;" ::: "memory");

            if (i + 1 < NSI) {   // prefetch next stage (overlaps MMA below)
                int i1 = i + 1;
                int kpos = i1 / 10, ck = i1 - kpos * 10;
                int dh = kpos / 3 - 1, dw = kpos % 3 - 1;
                if (tid < 128)
                    av = *(const int4*)(g_wq + ((size_t)kpos * COUT + co_base + rowT) * CIN + ck * 32 + half * 16);
                int hs = hB + dh, ws = wB + dw;
                bv = make_int4(0, 0, 0, 0);
                if (hs >= 0 && hs < 64 && ws >= 0 && ws < 64)
                    bv = *(const int4*)(g_xq + (size_t)((n << 12) + (hs << 6) + ws) * CIN + ck * 32 + half * 16);
            }

            uint32_t a[2][4], b[4][2];
#pragma unroll
            for (int mt = 0; mt < 2; mt++) {
                int row = warp_m * 32 + mt * 16 + rr;
                a[mt][0] = sA32[row * 8 + qq];
                a[mt][1] = sA32[(row + 8) * 8 + qq];
                a[mt][2] = sA32[row * 8 + 4 + qq];
                a[mt][3] = sA32[(row + 8) * 8 + 4 + qq];
            }
#pragma unroll
            for (int nt = 0; nt < 4; nt++) {
                int col = warp_n * 32 + nt * 8 + rr;
                b[nt][0] = sB32[col * 8 + qq];
                b[nt][1] = sB32[col * 8 + 4 + qq];
            }
#pragma unroll
            for (int mt = 0; mt < 2; mt++)
#pragma unroll
                for (int nt = 0; nt < 4; nt++)
                    mma_s8(acc[mt][nt], a[mt], b[nt]);
        }
    } else {
        // ======================= dp4a group =======================
        const int dtid = tid - 256;            // 0..127
        const int pig = dtid & 15;             // pixel group
        const int cog = dtid >> 4;             // co group (0..7)

        int accD[8][8];
#pragma unroll
        for (int a = 0; a < 8; a++)
#pragma unroll
            for (int b = 0; b < 8; b++) accD[a][b] = 0;

        const int rowD = dtid >> 1;            // 0..63
        const int halfD = dtid & 1;

        int4 avD, bv0, bv1;
        // prefetch stage 0 of dp4a stream (kpos = TAPS_I)
        {
            const int kpos = TAPS_I;
            const int dh = kpos / 3 - 1, dw = kpos % 3 - 1;
            avD = *(const int4*)(g_wq + ((size_t)kpos * COUT + co_base + rowD) * CIN + halfD * 16);
            int ws = (rowD & 63) + dw;
            int hs0 = H0 + dh, hs1 = H0 + 1 + dh;
            bv0 = make_int4(0, 0, 0, 0);
            bv1 = make_int4(0, 0, 0, 0);
            bool wok = (ws >= 0) && (ws < 64);
            if (wok && hs0 >= 0 && hs0 < 64)
                bv0 = *(const int4*)(g_xq + (size_t)((n << 12) + (hs0 << 6) + ws) * CIN + halfD * 16);
            if (wok && hs1 >= 0 && hs1 < 64)
                bv1 = *(const int4*)(g_xq + (size_t)((n << 12) + (hs1 << 6) + ws) * CIN + halfD * 16);
        }

        for (int i = 0; i < NSD; i++) {
            asm volatile("bar.sync 2, 128;" ::: "memory");
            *(int4*)(sAd + rowD * 32 + halfD * 16) = avD;
            *(int4*)(sBd + rowD * 32 + halfD * 16) = bv0;
            *(int4*)(sBd + (rowD + 64) * 32 + halfD * 16) = bv1;
            asm volatile("bar.sync 2, 128;" ::: "memory");

            if (i + 1 < NSD) {   // prefetch next
                int i1 = i + 1;
                int kpos = TAPS_I + i1 / 10, ck = i1 % 10;
                int dh = kpos / 3 - 1, dw = kpos % 3 - 1;
                avD = *(const int4*)(g_wq + ((size_t)kpos * COUT + co_base + rowD) * CIN + ck * 32 + halfD * 16);
                int ws = (rowD & 63) + dw;
                int hs0 = H0 + dh, hs1 = H0 + 1 + dh;
                bv0 = make_int4(0, 0, 0, 0);
                bv1 = make_int4(0, 0, 0, 0);
                bool wok = (ws >= 0) && (ws < 64);
                if (wok && hs0 >= 0 && hs0 < 64)
                    bv0 = *(const int4*)(g_xq + (size_t)((n << 12) + (hs0 << 6) + ws) * CIN + ck * 32 + halfD * 16);
                if (wok && hs1 >= 0 && hs1 < 64)
                    bv1 = *(const int4*)(g_xq + (size_t)((n << 12) + (hs1 << 6) + ws) * CIN + ck * 32 + halfD * 16);
            }

            // compute: 8co x 8pix, k = 32 bytes in four k8 steps
#pragma unroll
            for (int s = 0; s < 4; s++) {
                uint2 aq[8];
#pragma unroll
                for (int cj = 0; cj < 8; cj++)
                    aq[cj] = *(const uint2*)(sAd + (cog * 8 + cj) * 32 + s * 8);
#pragma unroll
                for (int j = 0; j < 8; j++) {
                    uint2 bq = *(const uint2*)(sBd + (pig + 16 * j) * 32 + s * 8);
#pragma unroll
                    for (int cj = 0; cj < 8; cj++) {
                        accD[cj][j] = __dp4a((int)aq[cj].x, (int)bq.x, accD[cj][j]);
                        accD[cj][j] = __dp4a((int)aq[cj].y, (int)bq.y, accD[cj][j]);
                    }
                }
            }
        }

        // write partials to smem
#pragma unroll
        for (int cj = 0; cj < 8; cj++)
#pragma unroll
            for (int j = 0; j < 8; j++)
                pint[(cog * 8 + cj) * 128 + pig + 16 * j] = accD[cj][j];
    }

    __syncthreads();

    // ======================= merge + epilogue (IMMA warps) =======================
    if (tid < 256) {
        const int wid = tid >> 5, lane = tid & 31;
        const int warp_m = wid >> 2, warp_n = wid & 3;
        const int qq = lane & 3, rr = lane >> 2;
        const float shift = *shift_ptr;
        const int ohw_base = pix_base & 4095;

#pragma unroll
        for (int mt = 0; mt < 2; mt++) {
#pragma unroll
            for (int hh = 0; hh < 2; hh++) {
                int co_l = warp_m * 32 + mt * 16 + rr + hh * 8;
                int co = co_base + co_l;
                float bb = g_bint8[co];
#pragma unroll
                for (int nt = 0; nt < 4; nt++) {
                    int pix_l = warp_n * 32 + nt * 8 + qq * 2;
                    int a0 = acc[mt][nt][hh * 2 + 0] + pint[co_l * 128 + pix_l];
                    int a1 = acc[mt][nt][hh * 2 + 1] + pint[co_l * 128 + pix_l + 1];
                    float v0 = clamp127(rintf(__int2float_rn(a0) * shift));
                    float v1 = clamp127(rintf(__int2float_rn(a1) * shift));
                    v0 = clamp127(v0 + bb);
                    v1 = clamp127(v1 + bb);
                    float* op = out + (((size_t)(n * COUT + co)) << 12) + ohw_base + pix_l;
                    *(float2*)op = make_float2(v0, v1);
                }
            }
        }
    }
}

// ---------------------------------------------------------------------------
extern "C" void kernel_launch(void* const* d_in, const int* in_sizes, int n_in,
                              void* d_out, int out_size) {
    const float* x = (const float*)d_in[0];
    const float* wt = (const float*)d_in[1];
    const float* bias = (const float*)d_in[2];
    const float* step_x = (const float*)d_in[3];
    const float* step_w = (const float*)d_in[4];
    const float* step_b = (const float*)d_in[5];
    const float* shift = (const float*)d_in[6];
    float* out = (float*)d_out;

    quant_x_kernel<<<dim3(1024, 5), 256>>>(x, step_x);

    int wtotal = KTAPS * COUT * CIN;
    quant_w_kernel<<<(wtotal + 255) / 256, 256>>>(wt, step_w);

    bias_kernel<<<2, 160>>>(bias, step_b, step_x, step_w, shift);

    conv_hybrid_kernel<<<dim3(NPIX / 128, COUT / 64), 384>>>(out, shift);
}

// round 4
// speedup vs baseline: 1.2089x; 1.0698x over previous
#include <cuda_runtime.h>
#include <stdint.h>

#define CIN   320
#define COUT  320
#define KTAPS 9
#define NPIX  65536
#define HWSZ  4096

// scratch (__device__ globals: allocation-free rule)
__device__ __align__(128) int8_t g_xq[(size_t)NPIX * CIN];          // [pix][ci]
__device__ __align__(128) int8_t g_wq[(size_t)KTAPS * COUT * CIN];  // [kpos][co][ci]
__device__ float g_bint8[COUT];

__device__ __forceinline__ float clamp127(float v) {
    return fminf(127.0f, fmaxf(-127.0f, v));
}

// ---------------------------------------------------------------------------
// Kernel 1: quantize x (NCHW fp32 -> NHWC int8) via smem transpose.
// ---------------------------------------------------------------------------
#define QP 80
__global__ __launch_bounds__(256) void quant_x_kernel(const float* __restrict__ x,
                                                      const float* __restrict__ step_x) {
    __shared__ int8_t s[64 * QP];
    const float st = *step_x;
    const int tid = threadIdx.x;
    const int ptile = blockIdx.x;
    const int ctile = blockIdx.y;
    const int n = ptile >> 6;
    const int hw0 = (ptile & 63) << 6;
    const float* xb = x + (((size_t)(n * CIN + ctile * 64)) << 12) + hw0;

#pragma unroll
    for (int k = 0; k < 4; k++) {
        int idx = tid + 256 * k;
        int ci = idx >> 4;
        int p4 = (idx & 15) << 2;
        float4 f = *(const float4*)(xb + (((size_t)ci) << 12) + p4);
        s[(p4 + 0) * QP + ci] = (int8_t)clamp127(rintf(__fdiv_rn(f.x, st)));
        s[(p4 + 1) * QP + ci] = (int8_t)clamp127(rintf(__fdiv_rn(f.y, st)));
        s[(p4 + 2) * QP + ci] = (int8_t)clamp127(rintf(__fdiv_rn(f.z, st)));
        s[(p4 + 3) * QP + ci] = (int8_t)clamp127(rintf(__fdiv_rn(f.w, st)));
    }
    __syncthreads();
    {
        int p = tid >> 2;
        int ch = (tid & 3) * 16;
        int4 v = *(const int4*)(s + p * QP + ch);
        *(int4*)(g_xq + (size_t)((n << 12) + hw0 + p) * CIN + ctile * 64 + ch) = v;
    }
}

// ---------------------------------------------------------------------------
// Kernel 2: quantize w  (OIHW fp32 -> [kpos][co][ci] int8)
// ---------------------------------------------------------------------------
__global__ void quant_w_kernel(const float* __restrict__ w,
                               const float* __restrict__ step_w) {
    float s = *step_w;
    int idx = blockIdx.x * 256 + threadIdx.x;
    if (idx >= KTAPS * COUT * CIN) return;
    int kpos = idx / (COUT * CIN);
    int r = idx % (COUT * CIN);
    int co = r / CIN;
    int ci = r % CIN;
    float v = clamp127(rintf(__fdiv_rn(w[(size_t)(co * CIN + ci) * KTAPS + kpos], s)));
    g_wq[idx] = (int8_t)v;
}

// ---------------------------------------------------------------------------
// Kernel 3: quantized bias
// ---------------------------------------------------------------------------
__global__ void bias_kernel(const float* __restrict__ bias,
                            const float* __restrict__ step_b,
                            const float* __restrict__ step_x,
                            const float* __restrict__ step_w,
                            const float* __restrict__ shift) {
    int co = blockIdx.x * blockDim.x + threadIdx.x;
    if (co >= COUT) return;
    float sb = *step_b;
    float xs = __fdiv_rn(1.0f, *step_x);
    float ws = __fdiv_rn(1.0f, *step_w);
    float sh = *shift;
    float bi = clamp127(rintf(__fdiv_rn(bias[co], sb)));
    float bdeq = __fmul_rn(bi, sb);
    float t = __fmul_rn(__fmul_rn(__fmul_rn(bdeq, sh), xs), ws);
    g_bint8[co] = clamp127(rintf(t));
}

// ---------------------------------------------------------------------------
// Kernel 4: HYBRID conv — 8 IMMA warps + 8 dp4a warps, block 512.
//   CTA tile 64co x 128pix.
//   warps 0..7  : mma.sync m16n8k32, taps 0..4   (50 stages, single buf, 2 bars)
//   warps 8..15 : dp4a 8co x 4pix,  taps 5..8    (40 stages, double buf, 1 bar)
// ---------------------------------------------------------------------------
#define TAPS_I 5
#define NSI (TAPS_I * 10)
#define NSD ((KTAPS - TAPS_I) * 10)
#define BSTR 48     // dp4a B-tile row stride (conflict-free for pig*48 pattern)

__device__ __forceinline__ void mma_s8(int* c, const uint32_t* a, const uint32_t* b) {
    asm volatile(
        "mma.sync.aligned.m16n8k32.row.col.s32.s8.s8.s32 "
        "{%0,%1,%2,%3}, {%4,%5,%6,%7}, {%8,%9}, {%0,%1,%2,%3};"
        : "+r"(c[0]), "+r"(c[1]), "+r"(c[2]), "+r"(c[3])
        : "r"(a[0]), "r"(a[1]), "r"(a[2]), "r"(a[3]),
          "r"(b[0]), "r"(b[1]));
}

__global__ __launch_bounds__(512, 1)
void conv_hybrid_kernel(float* __restrict__ out, const float* __restrict__ shift_ptr) {
    __shared__ __align__(16) int8_t sAi[64 * 32];          // IMMA weights
    __shared__ __align__(16) int8_t sBi[128 * 32];         // IMMA activations
    __shared__ __align__(16) int8_t sAd[2][64 * 32];       // dp4a weights (dbuf)
    __shared__ __align__(16) int8_t sBd[2][128 * BSTR];    // dp4a acts (dbuf, padded)
    __shared__ int pint[64 * 128];                         // dp4a partials [co][pix]

    const int tid = threadIdx.x;
    const int pix_base = blockIdx.x * 128;
    const int co_base = blockIdx.y * 64;
    const int n = pix_base >> 12;
    const int H0 = (pix_base & 4095) >> 6;      // CTA covers image rows H0, H0+1

    int acc[2][4][4];    // IMMA accs (tid<256)

    if (tid < 256) {
        // ============================ IMMA group ============================
        const int wid = tid >> 5, lane = tid & 31;
        const int warp_m = wid >> 2, warp_n = wid & 3;
        const int qq = lane & 3, rr = lane >> 2;
        const uint32_t* sA32 = (const uint32_t*)sAi;
        const uint32_t* sB32 = (const uint32_t*)sBi;

#pragma unroll
        for (int i = 0; i < 2; i++)
#pragma unroll
            for (int j = 0; j < 4; j++)
#pragma unroll
                for (int k = 0; k < 4; k++) acc[i][j][k] = 0;

        const int rowT = tid >> 1;
        const int half = tid & 1;
        const int hB = H0 + (rowT >> 6);
        const int wB = rowT & 63;

        int4 av, bv;
        {   // prefetch stage 0 (kpos=0: dh=-1, dw=-1, ck=0)
            if (tid < 128)
                av = *(const int4*)(g_wq + ((size_t)(co_base + rowT)) * CIN + half * 16);
            int hs = hB - 1, ws = wB - 1;
            bv = make_int4(0, 0, 0, 0);
            if (hs >= 0 && hs < 64 && ws >= 0 && ws < 64)
                bv = *(const int4*)(g_xq + (size_t)((n << 12) + (hs << 6) + ws) * CIN + half * 16);
        }

        for (int i = 0; i < NSI; i++) {
            asm volatile("bar.sync 1, 256;" ::: "memory");
            if (tid < 128) *(int4*)(sAi + rowT * 32 + half * 16) = av;
            *(int4*)(sBi + rowT * 32 + half * 16) = bv;
            asm volatile("bar.sync 1, 256;" ::: "memory");

            if (i + 1 < NSI) {
                int i1 = i + 1;
                int kpos = i1 / 10, ck = i1 - kpos * 10;
                int dh = kpos / 3 - 1, dw = kpos % 3 - 1;
                if (tid < 128)
                    av = *(const int4*)(g_wq + ((size_t)kpos * COUT + co_base + rowT) * CIN + ck * 32 + half * 16);
                int hs = hB + dh, ws = wB + dw;
                bv = make_int4(0, 0, 0, 0);
                if (hs >= 0 && hs < 64 && ws >= 0 && ws < 64)
                    bv = *(const int4*)(g_xq + (size_t)((n << 12) + (hs << 6) + ws) * CIN + ck * 32 + half * 16);
            }

            uint32_t a[2][4], b[4][2];
#pragma unroll
            for (int mt = 0; mt < 2; mt++) {
                int row = warp_m * 32 + mt * 16 + rr;
                a[mt][0] = sA32[row * 8 + qq];
                a[mt][1] = sA32[(row + 8) * 8 + qq];
                a[mt][2] = sA32[row * 8 + 4 + qq];
                a[mt][3] = sA32[(row + 8) * 8 + 4 + qq];
            }
#pragma unroll
            for (int nt = 0; nt < 4; nt++) {
                int col = warp_n * 32 + nt * 8 + rr;
                b[nt][0] = sB32[col * 8 + qq];
                b[nt][1] = sB32[col * 8 + 4 + qq];
            }
#pragma unroll
            for (int mt = 0; mt < 2; mt++)
#pragma unroll
                for (int nt = 0; nt < 4; nt++)
                    mma_s8(acc[mt][nt], a[mt], b[nt]);
        }
    } else {
        // ============================ dp4a group ============================
        const int dt = tid - 256;              // 0..255
        const int lane = dt & 31;
        const int cog = dt >> 5;               // warp-uniform co group, 0..7
        const int pig = lane;                  // pixel group, 0..31

        int accD[8][4];                        // [co][pix]
#pragma unroll
        for (int a = 0; a < 8; a++)
#pragma unroll
            for (int b = 0; b < 4; b++) accD[a][b] = 0;

        // stage-load geometry: B rows by (dt>>1, dt&1); A rows by (dt>>1 for dt<128)
        const int rowL = dt >> 1;              // 0..127
        const int halfL = dt & 1;
        const int hL = H0 + (rowL >> 6);
        const int wL = rowL & 63;

        int4 avD, bvD;
        {   // prefetch stage 0 (kpos = TAPS_I)
            const int kpos = TAPS_I;
            const int dh = kpos / 3 - 1, dw = kpos % 3 - 1;
            if (dt < 128)
                avD = *(const int4*)(g_wq + ((size_t)kpos * COUT + co_base + rowL) * CIN + halfL * 16);
            int hs = hL + dh, ws = wL + dw;
            bvD = make_int4(0, 0, 0, 0);
            if (hs >= 0 && hs < 64 && ws >= 0 && ws < 64)
                bvD = *(const int4*)(g_xq + (size_t)((n << 12) + (hs << 6) + ws) * CIN + halfL * 16);
        }
        // store stage 0 into slot 0
        if (dt < 128) *(int4*)(sAd[0] + rowL * 32 + halfL * 16) = avD;
        *(int4*)(sBd[0] + rowL * BSTR + halfL * 16) = bvD;

        for (int i = 0; i < NSD; i++) {
            asm volatile("bar.sync 2, 256;" ::: "memory");
            const int slot = i & 1;

            // prefetch stage i+1 from gmem (hidden under compute)
            if (i + 1 < NSD) {
                int i1 = i + 1;
                int kpos = TAPS_I + i1 / 10, ck = i1 % 10;
                int dh = kpos / 3 - 1, dw = kpos % 3 - 1;
                if (dt < 128)
                    avD = *(const int4*)(g_wq + ((size_t)kpos * COUT + co_base + rowL) * CIN + ck * 32 + halfL * 16);
                int hs = hL + dh, ws = wL + dw;
                bvD = make_int4(0, 0, 0, 0);
                if (hs >= 0 && hs < 64 && ws >= 0 && ws < 64)
                    bvD = *(const int4*)(g_xq + (size_t)((n << 12) + (hs << 6) + ws) * CIN + ck * 32 + halfL * 16);
            }

            // compute on slot: 8co x 4pix, K=32 bytes in two 16B halves
#pragma unroll
            for (int s16 = 0; s16 < 2; s16++) {
                int4 aq[8];
#pragma unroll
                for (int c = 0; c < 8; c++)
                    aq[c] = *(const int4*)(sAd[slot] + (cog * 8 + c) * 32 + s16 * 16);
#pragma unroll
                for (int jj = 0; jj < 4; jj++) {
                    int4 bq = *(const int4*)(sBd[slot] + (pig + 32 * jj) * BSTR + s16 * 16);
#pragma unroll
                    for (int c = 0; c < 8; c++) {
                        accD[c][jj] = __dp4a(aq[c].x, bq.x, accD[c][jj]);
                        accD[c][jj] = __dp4a(aq[c].y, bq.y, accD[c][jj]);
                        accD[c][jj] = __dp4a(aq[c].z, bq.z, accD[c][jj]);
                        accD[c][jj] = __dp4a(aq[c].w, bq.w, accD[c][jj]);
                    }
                }
            }

            // store stage i+1 into the other slot (safe: bar above retired i-1 reads)
            if (i + 1 < NSD) {
                const int ns = (i + 1) & 1;
                if (dt < 128) *(int4*)(sAd[ns] + rowL * 32 + halfL * 16) = avD;
                *(int4*)(sBd[ns] + rowL * BSTR + halfL * 16) = bvD;
            }
        }

        // write partials
#pragma unroll
        for (int c = 0; c < 8; c++)
#pragma unroll
            for (int jj = 0; jj < 4; jj++)
                pint[(cog * 8 + c) * 128 + pig + 32 * jj] = accD[c][jj];
    }

    __syncthreads();

    // =================== merge + epilogue (IMMA warps) ===================
    if (tid < 256) {
        const int wid = tid >> 5, lane = tid & 31;
        const int warp_m = wid >> 2, warp_n = wid & 3;
        const int qq = lane & 3, rr = lane >> 2;
        const float shift = *shift_ptr;
        const int ohw_base = pix_base & 4095;

#pragma unroll
        for (int mt = 0; mt < 2; mt++) {
#pragma unroll
            for (int hh = 0; hh < 2; hh++) {
                int co_l = warp_m * 32 + mt * 16 + rr + hh * 8;
                int co = co_base + co_l;
                float bb = g_bint8[co];
#pragma unroll
                for (int nt = 0; nt < 4; nt++) {
                    int pix_l = warp_n * 32 + nt * 8 + qq * 2;
                    int a0 = acc[mt][nt][hh * 2 + 0] + pint[co_l * 128 + pix_l];
                    int a1 = acc[mt][nt][hh * 2 + 1] + pint[co_l * 128 + pix_l + 1];
                    float v0 = clamp127(rintf(__int2float_rn(a0) * shift));
                    float v1 = clamp127(rintf(__int2float_rn(a1) * shift));
                    v0 = clamp127(v0 + bb);
                    v1 = clamp127(v1 + bb);
                    float* op = out + (((size_t)(n * COUT + co)) << 12) + ohw_base + pix_l;
                    *(float2*)op = make_float2(v0, v1);
                }
            }
        }
    }
}

// ---------------------------------------------------------------------------
extern "C" void kernel_launch(void* const* d_in, const int* in_sizes, int n_in,
                              void* d_out, int out_size) {
    const float* x = (const float*)d_in[0];
    const float* wt = (const float*)d_in[1];
    const float* bias = (const float*)d_in[2];
    const float* step_x = (const float*)d_in[3];
    const float* step_w = (const float*)d_in[4];
    const float* step_b = (const float*)d_in[5];
    const float* shift = (const float*)d_in[6];
    float* out = (float*)d_out;

    quant_x_kernel<<<dim3(1024, 5), 256>>>(x, step_x);

    int wtotal = KTAPS * COUT * CIN;
    quant_w_kernel<<<(wtotal + 255) / 256, 256>>>(wt, step_w);

    bias_kernel<<<2, 160>>>(bias, step_b, step_x, step_w, shift);

    conv_hybrid_kernel<<<dim3(NPIX / 128, COUT / 64), 512>>>(out, shift);
}